// round 1
// baseline (speedup 1.0000x reference)
#include <cuda_runtime.h>
#include <math.h>

#define SCALE_F 0.125f

__device__ float g_y[2ull * 8192 * 1536];
__device__ float g_q[2ull * 64 * 1024 * 64];
__device__ float g_k[2ull * 64 * 1024 * 64];
__device__ float g_vT[2ull * 64 * 64 * 1024];
__device__ float g_s[2ull * 64 * 1024 * 1024];
__device__ float g_attnh[2ull * 64 * 1024 * 64];
__device__ float g_att2[2ull * 8192 * 512];

// C_r[m][n] = alpha * sum_k ( Ar*Br + S1*Ai*Bi ) (+bias_r[n])
// C_i[m][n] = alpha * sum_k ( Ai*Br + S2*Ar*Bi ) (+bias_i[n])
template<int S1, int S2, bool BIAS>
__global__ __launch_bounds__(256, 2)
void gemm_cplx(const float* __restrict__ Ar, const float* __restrict__ Ai,
               const float* __restrict__ Br, const float* __restrict__ Bi,
               const float* __restrict__ bR, const float* __restrict__ bI,
               float* __restrict__ Cr, float* __restrict__ Ci,
               int N, int K, float alpha,
               long long bsA, long long bsB, long long bsC)
{
    __shared__ float sAr[16][128];
    __shared__ float sAi[16][128];
    __shared__ float sBr[16][64];
    __shared__ float sBi[16][64];

    const int tid = threadIdx.x;
    const int tx = tid & 15;
    const int ty = tid >> 4;
    const int m0 = blockIdx.y * 128;
    const int n0 = blockIdx.x * 64;

    Ar += (long long)blockIdx.z * bsA;  Ai += (long long)blockIdx.z * bsA;
    Br += (long long)blockIdx.z * bsB;  Bi += (long long)blockIdx.z * bsB;
    Cr += (long long)blockIdx.z * bsC;  Ci += (long long)blockIdx.z * bsC;

    float accr[8][4];
    float acci[8][4];
    #pragma unroll
    for (int i = 0; i < 8; i++)
        #pragma unroll
        for (int j = 0; j < 4; j++) { accr[i][j] = 0.f; acci[i][j] = 0.f; }

    for (int k0 = 0; k0 < K; k0 += 16) {
        #pragma unroll
        for (int e = 0; e < 2; e++) {
            int qq  = tid * 2 + e;
            int row = qq >> 2;
            int kq  = (qq & 3) * 4;
            long long off = (long long)(m0 + row) * K + k0 + kq;
            float4 v = *(const float4*)(Ar + off);
            sAr[kq + 0][row] = v.x; sAr[kq + 1][row] = v.y;
            sAr[kq + 2][row] = v.z; sAr[kq + 3][row] = v.w;
            float4 w = *(const float4*)(Ai + off);
            sAi[kq + 0][row] = w.x; sAi[kq + 1][row] = w.y;
            sAi[kq + 2][row] = w.z; sAi[kq + 3][row] = w.w;
        }
        {
            int row = tid >> 2;
            int kq  = (tid & 3) * 4;
            long long off = (long long)(n0 + row) * K + k0 + kq;
            float4 v = *(const float4*)(Br + off);
            sBr[kq + 0][row] = v.x; sBr[kq + 1][row] = v.y;
            sBr[kq + 2][row] = v.z; sBr[kq + 3][row] = v.w;
            float4 w = *(const float4*)(Bi + off);
            sBi[kq + 0][row] = w.x; sBi[kq + 1][row] = w.y;
            sBi[kq + 2][row] = w.z; sBi[kq + 3][row] = w.w;
        }
        __syncthreads();

        #pragma unroll 4
        for (int kk = 0; kk < 16; kk++) {
            float4 a0r = ((const float4*)sAr[kk])[ty * 2];
            float4 a1r = ((const float4*)sAr[kk])[ty * 2 + 1];
            float4 a0i = ((const float4*)sAi[kk])[ty * 2];
            float4 a1i = ((const float4*)sAi[kk])[ty * 2 + 1];
            float4 b4r = ((const float4*)sBr[kk])[tx];
            float4 b4i = ((const float4*)sBi[kk])[tx];
            float arv[8] = {a0r.x, a0r.y, a0r.z, a0r.w, a1r.x, a1r.y, a1r.z, a1r.w};
            float aiv[8] = {a0i.x, a0i.y, a0i.z, a0i.w, a1i.x, a1i.y, a1i.z, a1i.w};
            float brv[4] = {b4r.x, b4r.y, b4r.z, b4r.w};
            float biv[4] = {b4i.x, b4i.y, b4i.z, b4i.w};
            #pragma unroll
            for (int i = 0; i < 8; i++) {
                #pragma unroll
                for (int j = 0; j < 4; j++) {
                    accr[i][j] = fmaf(arv[i], brv[j], accr[i][j]);
                    accr[i][j] = (S1 > 0) ? fmaf(aiv[i],  biv[j], accr[i][j])
                                          : fmaf(-aiv[i], biv[j], accr[i][j]);
                    acci[i][j] = fmaf(aiv[i], brv[j], acci[i][j]);
                    acci[i][j] = (S2 > 0) ? fmaf(arv[i],  biv[j], acci[i][j])
                                          : fmaf(-arv[i], biv[j], acci[i][j]);
                }
            }
        }
        __syncthreads();
    }

    #pragma unroll
    for (int i = 0; i < 8; i++) {
        long long m = m0 + ty * 8 + i;
        int n = n0 + tx * 4;
        float4 vr, vi;
        vr.x = accr[i][0] * alpha; vr.y = accr[i][1] * alpha;
        vr.z = accr[i][2] * alpha; vr.w = accr[i][3] * alpha;
        vi.x = acci[i][0] * alpha; vi.y = acci[i][1] * alpha;
        vi.z = acci[i][2] * alpha; vi.w = acci[i][3] * alpha;
        if (BIAS) {
            vr.x += bR[n + 0]; vr.y += bR[n + 1]; vr.z += bR[n + 2]; vr.w += bR[n + 3];
            vi.x += bI[n + 0]; vi.y += bI[n + 1]; vi.z += bI[n + 2]; vi.w += bI[n + 3];
        }
        *(float4*)(Cr + m * N + n) = vr;
        *(float4*)(Ci + m * N + n) = vi;
    }
}

__global__ __launch_bounds__(256)
void reshape_qk_kernel(const float* __restrict__ y, float* __restrict__ q, float* __restrict__ k)
{
    long long idx = (long long)blockIdx.x * 256 + threadIdx.x;   // < 2^24
    int n       = (int)(idx & 1023);
    long long m = (idx >> 10) & 8191;
    int ri      = (int)(idx >> 23);
    float val = y[(long long)ri * 8192 * 1536 + m * 1536 + n];
    int t = (int)(m >> 3), b = (int)(m & 7);
    int sec = n >> 9, e = n & 511;
    int h = e >> 6, d = e & 63;
    long long dst = (((long long)ri * 64 + b * 8 + h) * 1024 + t) * 64 + d;
    (sec ? k : q)[dst] = val;
}

__global__ void transpose_v_kernel(const float* __restrict__ y, float* __restrict__ vT)
{
    __shared__ float tile[32][33];
    int zb = blockIdx.z;
    int ri = zb >> 6, bh = zb & 63;
    int b = bh >> 3, h = bh & 7;
    int t0 = blockIdx.x * 32, d0 = blockIdx.y * 32;
    const float* src = y + (long long)ri * 8192 * 1536 + 1024 + (long long)h * 64 + d0;
    #pragma unroll
    for (int r = 0; r < 32; r += 8) {
        int tloc = threadIdx.y + r;
        long long m = (long long)(t0 + tloc) * 8 + b;
        tile[tloc][threadIdx.x] = src[m * 1536 + threadIdx.x];
    }
    __syncthreads();
    float* dst = vT + (((long long)ri * 64 + bh) * 64 + d0) * 1024 + t0;
    #pragma unroll
    for (int r = 0; r < 32; r += 8) {
        int d = threadIdx.y + r;
        dst[(long long)d * 1024 + threadIdx.x] = tile[threadIdx.x][d];
    }
}

__global__ __launch_bounds__(128)
void softmax_kernel(float* __restrict__ sp)
{
    float4* p4 = (float4*)(sp + (long long)blockIdx.x * 1024);
    int t = threadIdx.x;
    float4 v0 = p4[t];
    float4 v1 = p4[t + 128];
    float mx = fmaxf(fmaxf(fmaxf(v0.x, v0.y), fmaxf(v0.z, v0.w)),
                     fmaxf(fmaxf(v1.x, v1.y), fmaxf(v1.z, v1.w)));
    #pragma unroll
    for (int o = 16; o > 0; o >>= 1)
        mx = fmaxf(mx, __shfl_xor_sync(0xffffffffu, mx, o));
    __shared__ float redm[4];
    __shared__ float reds[4];
    int w = t >> 5;
    if ((t & 31) == 0) redm[w] = mx;
    __syncthreads();
    mx = fmaxf(fmaxf(redm[0], redm[1]), fmaxf(redm[2], redm[3]));

    float e[8];
    e[0] = __expf(v0.x - mx); e[1] = __expf(v0.y - mx);
    e[2] = __expf(v0.z - mx); e[3] = __expf(v0.w - mx);
    e[4] = __expf(v1.x - mx); e[5] = __expf(v1.y - mx);
    e[6] = __expf(v1.z - mx); e[7] = __expf(v1.w - mx);
    float sum = ((e[0] + e[1]) + (e[2] + e[3])) + ((e[4] + e[5]) + (e[6] + e[7]));
    #pragma unroll
    for (int o = 16; o > 0; o >>= 1)
        sum += __shfl_xor_sync(0xffffffffu, sum, o);
    if ((t & 31) == 0) reds[w] = sum;
    __syncthreads();
    sum = (reds[0] + reds[1]) + (reds[2] + reds[3]);
    float inv = 1.0f / sum;
    v0.x = e[0] * inv; v0.y = e[1] * inv; v0.z = e[2] * inv; v0.w = e[3] * inv;
    v1.x = e[4] * inv; v1.y = e[5] * inv; v1.z = e[6] * inv; v1.w = e[7] * inv;
    p4[t] = v0;
    p4[t + 128] = v1;
}

__global__ __launch_bounds__(256)
void avg_kernel(const float* __restrict__ s, float* __restrict__ out)
{
    long long idx = (long long)blockIdx.x * 256 + threadIdx.x;   // < 2^22 float4s
    int s4 = (int)(idx & 255);
    int t  = (int)((idx >> 8) & 1023);
    int b  = (int)((idx >> 18) & 7);
    int ri = (int)(idx >> 21);
    float4 acc = make_float4(0.f, 0.f, 0.f, 0.f);
    #pragma unroll
    for (int h = 0; h < 8; h++) {
        const float4* src =
            (const float4*)(s + (((long long)ri * 64 + b * 8 + h) * 1024 + t) * 1024) + s4;
        float4 v = *src;
        acc.x += v.x; acc.y += v.y; acc.z += v.z; acc.w += v.w;
    }
    acc.x *= 0.125f; acc.y *= 0.125f; acc.z *= 0.125f; acc.w *= 0.125f;
    ((float4*)out)[idx] = acc;
}

__global__ __launch_bounds__(256)
void reshape_attn_kernel(const float* __restrict__ attnh, float* __restrict__ att2)
{
    long long idx = (long long)blockIdx.x * 256 + threadIdx.x;   // < 2^23
    int e       = (int)(idx & 511);
    long long m = (idx >> 9) & 8191;
    int ri      = (int)(idx >> 22);
    int t = (int)(m >> 3), b = (int)(m & 7);
    int h = e >> 6, d = e & 63;
    att2[idx] = attnh[(((long long)ri * 64 + b * 8 + h) * 1024 + t) * 64 + d];
}

extern "C" void kernel_launch(void* const* d_in, const int* in_sizes, int n_in,
                              void* d_out, int out_size)
{
    const float* xr   = (const float*)d_in[0];
    const float* xi   = (const float*)d_in[1];
    const float* Wqr  = (const float*)d_in[2];
    const float* Wqi  = (const float*)d_in[3];
    const float* bqr  = (const float*)d_in[4];
    const float* bqi  = (const float*)d_in[5];
    const float* Wor  = (const float*)d_in[6];
    const float* Woi  = (const float*)d_in[7];
    const float* bor_ = (const float*)d_in[8];
    const float* boi  = (const float*)d_in[9];
    float* out = (float*)d_out;

    float *y, *q, *k, *vT, *s, *attnh, *att2;
    cudaGetSymbolAddress((void**)&y, g_y);
    cudaGetSymbolAddress((void**)&q, g_q);
    cudaGetSymbolAddress((void**)&k, g_k);
    cudaGetSymbolAddress((void**)&vT, g_vT);
    cudaGetSymbolAddress((void**)&s, g_s);
    cudaGetSymbolAddress((void**)&attnh, g_attnh);
    cudaGetSymbolAddress((void**)&att2, g_att2);

    const long long RI_Y    = 8192LL * 1536;
    const long long RI_HEAD = 64LL * 1024 * 64;
    const long long RI_S    = 64LL * 1024 * 1024;
    const long long RI_OUT  = 8192LL * 512;

    // 1) QKV complex projection
    gemm_cplx<-1, 1, true><<<dim3(24, 64, 1), 256>>>(
        xr, xi, Wqr, Wqi, bqr, bqi, y, y + RI_Y, 1536, 512, 1.0f, 0, 0, 0);

    // 2) head-layout reshapes
    reshape_qk_kernel<<<65536, 256>>>(y, q, k);
    transpose_v_kernel<<<dim3(32, 2, 128), dim3(32, 8)>>>(y, vT);

    // 3) scores (batched over 64 heads): plus/minus parts
    gemm_cplx<1, -1, false><<<dim3(16, 8, 64), 256>>>(
        q, q + RI_HEAD, k, k + RI_HEAD, nullptr, nullptr,
        s, s + RI_S, 1024, 64, SCALE_F,
        1024LL * 64, 1024LL * 64, 1024LL * 1024);

    // 4) softmax in place over all 2*64*1024 rows
    softmax_kernel<<<131072, 128>>>(s);

    // 5) head-averaged attention weights into d_out tail
    avg_kernel<<<16384, 256>>>(s, out + 2LL * 8192 * 512);

    // 6) PV (batched over 64 heads)
    gemm_cplx<1, -1, false><<<dim3(1, 8, 64), 256>>>(
        s, s + RI_S, vT, vT + RI_HEAD, nullptr, nullptr,
        attnh, attnh + RI_HEAD, 64, 1024, 1.0f,
        1024LL * 1024, 64LL * 1024, 1024LL * 64);

    // 7) reshape attn to [ri][m][e]
    reshape_attn_kernel<<<32768, 256>>>(attnh, att2);

    // 8) output projection into d_out head
    gemm_cplx<-1, 1, true><<<dim3(8, 64, 1), 256>>>(
        att2, att2 + RI_OUT, Wor, Woi, bor_, boi,
        out, out + RI_OUT, 512, 512, 1.0f, 0, 0, 0);
}

// round 2
// speedup vs baseline: 2.4236x; 2.4236x over previous
#include <cuda_runtime.h>
#include <stdint.h>
#include <math.h>

#define SCALE_F 0.125f

__device__ float g_y[2ull * 8192 * 1536];
__device__ float g_q[2ull * 64 * 1024 * 64];
__device__ float g_k[2ull * 64 * 1024 * 64];
__device__ float g_vT[2ull * 64 * 64 * 1024];
__device__ float g_s[2ull * 64 * 1024 * 1024];
__device__ float g_attnh[2ull * 64 * 1024 * 64];
__device__ float g_att2[2ull * 8192 * 512];

__device__ __forceinline__ uint32_t f2tf32(float f) {
    uint32_t u;
    asm("cvt.rna.tf32.f32 %0, %1;" : "=r"(u) : "f"(f));
    return u;
}

#define MMA_TF32(C, A, B) \
    asm volatile("mma.sync.aligned.m16n8k8.row.col.f32.tf32.tf32.f32 " \
                 "{%0,%1,%2,%3},{%4,%5,%6,%7},{%8,%9},{%0,%1,%2,%3};" \
                 : "+f"((C)[0]), "+f"((C)[1]), "+f"((C)[2]), "+f"((C)[3]) \
                 : "r"((A)[0]), "r"((A)[1]), "r"((A)[2]), "r"((A)[3]), \
                   "r"((B)[0]), "r"((B)[1]))

// C_r = alpha*(Ar.Br^T + S1*Ai.Bi^T) (+bias_r) ; C_i = alpha*(Ai.Br^T + S2*Ar.Bi^T) (+bias_i)
// A: [M][K] row-major, B: [N][K] row-major. BM=128, BN=64, BK=16. 256 threads, 8 warps 4x2.
template<int S1, int S2, bool BIAS>
__global__ __launch_bounds__(256, 2)
void gemm_cplx_mma(const float* __restrict__ Ar, const float* __restrict__ Ai,
                   const float* __restrict__ Br, const float* __restrict__ Bi,
                   const float* __restrict__ bR, const float* __restrict__ bI,
                   float* __restrict__ Cr, float* __restrict__ Ci,
                   int N, int K, float alpha,
                   long long bsA, long long bsB, long long bsC)
{
    __shared__ uint32_t sAr[128 * 20];
    __shared__ uint32_t sAi[128 * 20];
    __shared__ uint32_t sBr[64 * 20];
    __shared__ uint32_t sBi[64 * 20];

    const int tid  = threadIdx.x;
    const int lane = tid & 31;
    const int wid  = tid >> 5;
    const int wm   = (wid >> 1) * 32;   // warp m offset within CTA tile
    const int wn   = (wid & 1) * 32;    // warp n offset
    const int g    = lane >> 2;         // 0..7
    const int t    = lane & 3;          // 0..3
    const int m0   = blockIdx.y * 128;
    const int n0   = blockIdx.x * 64;

    Ar += (long long)blockIdx.z * bsA;  Ai += (long long)blockIdx.z * bsA;
    Br += (long long)blockIdx.z * bsB;  Bi += (long long)blockIdx.z * bsB;
    Cr += (long long)blockIdx.z * bsC;  Ci += (long long)blockIdx.z * bsC;

    float cr[2][4][4];
    float ci[2][4][4];
    #pragma unroll
    for (int a = 0; a < 2; a++)
        #pragma unroll
        for (int b = 0; b < 4; b++)
            #pragma unroll
            for (int c = 0; c < 4; c++) { cr[a][b][c] = 0.f; ci[a][b][c] = 0.f; }

    for (int k0 = 0; k0 < K; k0 += 16) {
        // A tile: 128x16 -> 512 float4, 2 per thread (each array)
        #pragma unroll
        for (int e = 0; e < 2; e++) {
            int idx = tid + e * 256;
            int row = idx >> 2;
            int kq  = (idx & 3) * 4;
            long long off = (long long)(m0 + row) * K + k0 + kq;
            float4 v = *(const float4*)(Ar + off);
            uint4 u;
            u.x = f2tf32(v.x); u.y = f2tf32(v.y); u.z = f2tf32(v.z); u.w = f2tf32(v.w);
            *(uint4*)(&sAr[row * 20 + kq]) = u;
            float4 w = *(const float4*)(Ai + off);
            u.x = f2tf32(w.x); u.y = f2tf32(w.y); u.z = f2tf32(w.z); u.w = f2tf32(w.w);
            *(uint4*)(&sAi[row * 20 + kq]) = u;
        }
        // B tile: 64x16 -> 256 float4, 1 per thread (each array)
        {
            int row = tid >> 2;
            int kq  = (tid & 3) * 4;
            long long off = (long long)(n0 + row) * K + k0 + kq;
            float4 v = *(const float4*)(Br + off);
            uint4 u;
            u.x = f2tf32(v.x); u.y = f2tf32(v.y); u.z = f2tf32(v.z); u.w = f2tf32(v.w);
            *(uint4*)(&sBr[row * 20 + kq]) = u;
            float4 w = *(const float4*)(Bi + off);
            u.x = f2tf32(w.x); u.y = f2tf32(w.y); u.z = f2tf32(w.z); u.w = f2tf32(w.w);
            *(uint4*)(&sBi[row * 20 + kq]) = u;
        }
        __syncthreads();

        #pragma unroll
        for (int kk = 0; kk < 16; kk += 8) {
            uint32_t far[2][4], fai[2][4], fbr[4][2], fbi[4][2];
            #pragma unroll
            for (int mt = 0; mt < 2; mt++) {
                int base = (wm + mt * 16 + g) * 20 + kk + t;
                far[mt][0] = sAr[base];
                far[mt][1] = sAr[base + 8 * 20];
                far[mt][2] = sAr[base + 4];
                far[mt][3] = sAr[base + 8 * 20 + 4];
                fai[mt][0] = sAi[base];
                fai[mt][1] = sAi[base + 8 * 20];
                fai[mt][2] = sAi[base + 4];
                fai[mt][3] = sAi[base + 8 * 20 + 4];
            }
            #pragma unroll
            for (int nt = 0; nt < 4; nt++) {
                int nb = (wn + nt * 8 + g) * 20 + kk + t;
                fbr[nt][0] = sBr[nb];
                fbr[nt][1] = sBr[nb + 4];
                fbi[nt][0] = sBi[nb];
                fbi[nt][1] = sBi[nb + 4];
            }
            #pragma unroll
            for (int mt = 0; mt < 2; mt++)
                #pragma unroll
                for (int nt = 0; nt < 4; nt++) {
                    MMA_TF32(cr[mt][nt], far[mt], fbr[nt]);
                    MMA_TF32(ci[mt][nt], fai[mt], fbr[nt]);
                }
            // Bi chains with sign handling: first the '+' chain, then flip sign bit, then '-' chain
            if (S2 > 0) {
                #pragma unroll
                for (int mt = 0; mt < 2; mt++)
                    #pragma unroll
                    for (int nt = 0; nt < 4; nt++)
                        MMA_TF32(ci[mt][nt], far[mt], fbi[nt]);   // Ci += Ar*Bi
            } else {
                #pragma unroll
                for (int mt = 0; mt < 2; mt++)
                    #pragma unroll
                    for (int nt = 0; nt < 4; nt++)
                        MMA_TF32(cr[mt][nt], fai[mt], fbi[nt]);   // Cr += Ai*Bi
            }
            #pragma unroll
            for (int nt = 0; nt < 4; nt++) {
                fbi[nt][0] ^= 0x80000000u;
                fbi[nt][1] ^= 0x80000000u;
            }
            if (S2 > 0) {
                #pragma unroll
                for (int mt = 0; mt < 2; mt++)
                    #pragma unroll
                    for (int nt = 0; nt < 4; nt++)
                        MMA_TF32(cr[mt][nt], fai[mt], fbi[nt]);   // Cr += Ai*(-Bi)
            } else {
                #pragma unroll
                for (int mt = 0; mt < 2; mt++)
                    #pragma unroll
                    for (int nt = 0; nt < 4; nt++)
                        MMA_TF32(ci[mt][nt], far[mt], fbi[nt]);   // Ci += Ar*(-Bi)
            }
        }
        __syncthreads();
    }

    #pragma unroll
    for (int mt = 0; mt < 2; mt++) {
        #pragma unroll
        for (int nt = 0; nt < 4; nt++) {
            int col = n0 + wn + nt * 8 + 2 * t;
            long long r0 = m0 + wm + mt * 16 + g;
            float b_r0 = 0.f, b_r1 = 0.f, b_i0 = 0.f, b_i1 = 0.f;
            if (BIAS) { b_r0 = bR[col]; b_r1 = bR[col + 1]; b_i0 = bI[col]; b_i1 = bI[col + 1]; }
            float2 v;
            v.x = cr[mt][nt][0] * alpha + b_r0; v.y = cr[mt][nt][1] * alpha + b_r1;
            *(float2*)(Cr + r0 * N + col) = v;
            v.x = cr[mt][nt][2] * alpha + b_r0; v.y = cr[mt][nt][3] * alpha + b_r1;
            *(float2*)(Cr + (r0 + 8) * N + col) = v;
            v.x = ci[mt][nt][0] * alpha + b_i0; v.y = ci[mt][nt][1] * alpha + b_i1;
            *(float2*)(Ci + r0 * N + col) = v;
            v.x = ci[mt][nt][2] * alpha + b_i0; v.y = ci[mt][nt][3] * alpha + b_i1;
            *(float2*)(Ci + (r0 + 8) * N + col) = v;
        }
    }
}

__global__ __launch_bounds__(256)
void reshape_qk_kernel(const float* __restrict__ y, float* __restrict__ q, float* __restrict__ k)
{
    long long idx = (long long)blockIdx.x * 256 + threadIdx.x;   // < 2^24
    int n       = (int)(idx & 1023);
    long long m = (idx >> 10) & 8191;
    int ri      = (int)(idx >> 23);
    float val = y[(long long)ri * 8192 * 1536 + m * 1536 + n];
    int t = (int)(m >> 3), b = (int)(m & 7);
    int sec = n >> 9, e = n & 511;
    int h = e >> 6, d = e & 63;
    long long dst = (((long long)ri * 64 + b * 8 + h) * 1024 + t) * 64 + d;
    (sec ? k : q)[dst] = val;
}

__global__ void transpose_v_kernel(const float* __restrict__ y, float* __restrict__ vT)
{
    __shared__ float tile[32][33];
    int zb = blockIdx.z;
    int ri = zb >> 6, bh = zb & 63;
    int b = bh >> 3, h = bh & 7;
    int t0 = blockIdx.x * 32, d0 = blockIdx.y * 32;
    const float* src = y + (long long)ri * 8192 * 1536 + 1024 + (long long)h * 64 + d0;
    #pragma unroll
    for (int r = 0; r < 32; r += 8) {
        int tloc = threadIdx.y + r;
        long long m = (long long)(t0 + tloc) * 8 + b;
        tile[tloc][threadIdx.x] = src[m * 1536 + threadIdx.x];
    }
    __syncthreads();
    float* dst = vT + (((long long)ri * 64 + bh) * 64 + d0) * 1024 + t0;
    #pragma unroll
    for (int r = 0; r < 32; r += 8) {
        int d = threadIdx.y + r;
        dst[(long long)d * 1024 + threadIdx.x] = tile[threadIdx.x][d];
    }
}

__global__ __launch_bounds__(128)
void softmax_kernel(float* __restrict__ sp)
{
    float4* p4 = (float4*)(sp + (long long)blockIdx.x * 1024);
    int t = threadIdx.x;
    float4 v0 = p4[t];
    float4 v1 = p4[t + 128];
    float mx = fmaxf(fmaxf(fmaxf(v0.x, v0.y), fmaxf(v0.z, v0.w)),
                     fmaxf(fmaxf(v1.x, v1.y), fmaxf(v1.z, v1.w)));
    #pragma unroll
    for (int o = 16; o > 0; o >>= 1)
        mx = fmaxf(mx, __shfl_xor_sync(0xffffffffu, mx, o));
    __shared__ float redm[4];
    __shared__ float reds[4];
    int w = t >> 5;
    if ((t & 31) == 0) redm[w] = mx;
    __syncthreads();
    mx = fmaxf(fmaxf(redm[0], redm[1]), fmaxf(redm[2], redm[3]));

    float e[8];
    e[0] = __expf(v0.x - mx); e[1] = __expf(v0.y - mx);
    e[2] = __expf(v0.z - mx); e[3] = __expf(v0.w - mx);
    e[4] = __expf(v1.x - mx); e[5] = __expf(v1.y - mx);
    e[6] = __expf(v1.z - mx); e[7] = __expf(v1.w - mx);
    float sum = ((e[0] + e[1]) + (e[2] + e[3])) + ((e[4] + e[5]) + (e[6] + e[7]));
    #pragma unroll
    for (int o = 16; o > 0; o >>= 1)
        sum += __shfl_xor_sync(0xffffffffu, sum, o);
    if ((t & 31) == 0) reds[w] = sum;
    __syncthreads();
    sum = (reds[0] + reds[1]) + (reds[2] + reds[3]);
    float inv = 1.0f / sum;
    v0.x = e[0] * inv; v0.y = e[1] * inv; v0.z = e[2] * inv; v0.w = e[3] * inv;
    v1.x = e[4] * inv; v1.y = e[5] * inv; v1.z = e[6] * inv; v1.w = e[7] * inv;
    p4[t] = v0;
    p4[t + 128] = v1;
}

__global__ __launch_bounds__(256)
void avg_kernel(const float* __restrict__ s, float* __restrict__ out)
{
    long long idx = (long long)blockIdx.x * 256 + threadIdx.x;   // < 2^22 float4s
    int s4 = (int)(idx & 255);
    int t  = (int)((idx >> 8) & 1023);
    int b  = (int)((idx >> 18) & 7);
    int ri = (int)(idx >> 21);
    float4 acc = make_float4(0.f, 0.f, 0.f, 0.f);
    #pragma unroll
    for (int h = 0; h < 8; h++) {
        const float4* src =
            (const float4*)(s + (((long long)ri * 64 + b * 8 + h) * 1024 + t) * 1024) + s4;
        float4 v = *src;
        acc.x += v.x; acc.y += v.y; acc.z += v.z; acc.w += v.w;
    }
    acc.x *= 0.125f; acc.y *= 0.125f; acc.z *= 0.125f; acc.w *= 0.125f;
    ((float4*)out)[idx] = acc;
}

__global__ __launch_bounds__(256)
void reshape_attn_kernel(const float* __restrict__ attnh, float* __restrict__ att2)
{
    long long idx = (long long)blockIdx.x * 256 + threadIdx.x;   // < 2^23
    int e       = (int)(idx & 511);
    long long m = (idx >> 9) & 8191;
    int ri      = (int)(idx >> 22);
    int t = (int)(m >> 3), b = (int)(m & 7);
    int h = e >> 6, d = e & 63;
    att2[idx] = attnh[(((long long)ri * 64 + b * 8 + h) * 1024 + t) * 64 + d];
}

extern "C" void kernel_launch(void* const* d_in, const int* in_sizes, int n_in,
                              void* d_out, int out_size)
{
    const float* xr   = (const float*)d_in[0];
    const float* xi   = (const float*)d_in[1];
    const float* Wqr  = (const float*)d_in[2];
    const float* Wqi  = (const float*)d_in[3];
    const float* bqr  = (const float*)d_in[4];
    const float* bqi  = (const float*)d_in[5];
    const float* Wor  = (const float*)d_in[6];
    const float* Woi  = (const float*)d_in[7];
    const float* bor_ = (const float*)d_in[8];
    const float* boi  = (const float*)d_in[9];
    float* out = (float*)d_out;

    float *y, *q, *k, *vT, *s, *attnh, *att2;
    cudaGetSymbolAddress((void**)&y, g_y);
    cudaGetSymbolAddress((void**)&q, g_q);
    cudaGetSymbolAddress((void**)&k, g_k);
    cudaGetSymbolAddress((void**)&vT, g_vT);
    cudaGetSymbolAddress((void**)&s, g_s);
    cudaGetSymbolAddress((void**)&attnh, g_attnh);
    cudaGetSymbolAddress((void**)&att2, g_att2);

    const long long RI_Y    = 8192LL * 1536;
    const long long RI_HEAD = 64LL * 1024 * 64;
    const long long RI_S    = 64LL * 1024 * 1024;
    const long long RI_OUT  = 8192LL * 512;

    // 1) QKV complex projection  (S1=-1, S2=+1)
    gemm_cplx_mma<-1, 1, true><<<dim3(24, 64, 1), 256>>>(
        xr, xi, Wqr, Wqi, bqr, bqi, y, y + RI_Y, 1536, 512, 1.0f, 0, 0, 0);

    // 2) head-layout reshapes
    reshape_qk_kernel<<<65536, 256>>>(y, q, k);
    transpose_v_kernel<<<dim3(32, 2, 128), dim3(32, 8)>>>(y, vT);

    // 3) scores (batched over 64 heads)  (S1=+1, S2=-1)
    gemm_cplx_mma<1, -1, false><<<dim3(16, 8, 64), 256>>>(
        q, q + RI_HEAD, k, k + RI_HEAD, nullptr, nullptr,
        s, s + RI_S, 1024, 64, SCALE_F,
        1024LL * 64, 1024LL * 64, 1024LL * 1024);

    // 4) softmax in place over all 2*64*1024 rows
    softmax_kernel<<<131072, 128>>>(s);

    // 5) head-averaged attention weights into d_out tail
    avg_kernel<<<16384, 256>>>(s, out + 2LL * 8192 * 512);

    // 6) PV (batched over 64 heads)  (S1=+1, S2=-1)
    gemm_cplx_mma<1, -1, false><<<dim3(1, 8, 64), 256>>>(
        s, s + RI_S, vT, vT + RI_HEAD, nullptr, nullptr,
        attnh, attnh + RI_HEAD, 64, 1024, 1.0f,
        1024LL * 1024, 64LL * 1024, 1024LL * 64);

    // 7) reshape attn to [ri][m][e]
    reshape_attn_kernel<<<32768, 256>>>(attnh, att2);

    // 8) output projection into d_out head  (S1=-1, S2=+1)
    gemm_cplx_mma<-1, 1, true><<<dim3(8, 64, 1), 256>>>(
        att2, att2 + RI_OUT, Wor, Woi, bor_, boi,
        out, out + RI_OUT, 512, 512, 1.0f, 0, 0, 0);
}